// round 7
// baseline (speedup 1.0000x reference)
#include <cuda_runtime.h>
#include <math.h>

#define NMAX 50000
#define EMAX 800000

// ---------------- scratch (static device globals; no allocations) -------------
__device__ float g_XL1[NMAX * 128];
__device__ float g_XR1[NMAX * 128];
__device__ float g_H  [NMAX * 128];
__device__ float g_XL2[NMAX * 64];
__device__ float g_XR2[NMAX * 64];
__device__ float g_T  [NMAX * 128];
__device__ int   g_src[EMAX];
__device__ int   g_dst[EMAX];
__device__ int   g_csr[EMAX];
__device__ int   g_cnt[NMAX];
__device__ int   g_incl[NMAX];
__device__ int   g_rowptr[NMAX + 1];
__device__ int   g_cursor[NMAX + 2];
__device__ int   g_bsum[1024];
__device__ int   g_dummy[4];
__device__ int   g_is64;

// ---------------- zero + edge_index dtype detection ----------------------------
__global__ void zero_detect_kernel(const long long* __restrict__ ei, int E, int n) {
    int g = blockIdx.x * blockDim.x + threadIdx.x;
    if (g < n) g_cnt[g] = 0;
    if (g == 0) {
        int ok = 1;
        int m = E < 64 ? E : 64;
        for (int i = 0; i < m; i++) {
            long long v = ei[i];
            if (v < 0 || v >= NMAX) { ok = 0; break; }
        }
        g_is64 = ok;
    }
}

__global__ void hist_kernel(const void* __restrict__ eiv, int E, int n) {
    int e = blockIdx.x * blockDim.x + threadIdx.x;
    if (e >= E) return;
    int s, d;
    if (g_is64) {
        const long long* ei = (const long long*)eiv;
        s = (int)ei[e];
        d = (int)ei[(size_t)E + e];
    } else {
        const int* ei = (const int*)eiv;
        s = ei[e];
        d = ei[E + e];
    }
    if ((unsigned)s >= (unsigned)n || (unsigned)d >= (unsigned)n) { s = 0; d = 0; }
    g_src[e] = s;
    g_dst[e] = d;
    atomicAdd(&g_cnt[d], 1);
}

// per-block inclusive scan (blockDim = 1024); phase 0: cnt->incl,bsum
// phase 1: bsum->bsum (single block, in place)
__global__ void scan1_kernel(int n, int phase) {
    __shared__ int sh[1024];
    const int* in = (phase == 0) ? g_cnt : g_bsum;
    int* incl     = (phase == 0) ? g_incl : g_bsum;
    int* bsum     = (phase == 0) ? g_bsum : g_dummy;
    int g = blockIdx.x * 1024 + threadIdx.x;
    int v = (g < n) ? in[g] : 0;
    sh[threadIdx.x] = v;
    __syncthreads();
    for (int off = 1; off < 1024; off <<= 1) {
        int t = (threadIdx.x >= off) ? sh[threadIdx.x - off] : 0;
        __syncthreads();
        sh[threadIdx.x] += t;
        __syncthreads();
    }
    if (g < n) incl[g] = sh[threadIdx.x];
    if (threadIdx.x == 1023) bsum[blockIdx.x] = sh[1023];
}

__global__ void scan3_kernel(int n) {
    int g = blockIdx.x * blockDim.x + threadIdx.x;
    if (g == 0) { g_rowptr[0] = 0; g_cursor[0] = 0; }
    if (g < n) {
        int b = g >> 10;
        int v = g_incl[g] + (b > 0 ? g_bsum[b - 1] : 0);
        g_rowptr[g + 1] = v;
        g_cursor[g + 1] = v;
    }
}

__global__ void scatter_kernel(int E) {
    int e = blockIdx.x * blockDim.x + threadIdx.x;
    if (e >= E) return;
    int d = g_dst[e];
    int pos = atomicAdd(&g_cursor[d], 1);
    g_csr[pos] = g_src[e];
}

// ---------------- SGEMM: out[N x M] = X[N x K] @ W[K x M] (+bias,relu) --------
// Static shared memory only (<=48KB): K tiled in chunks of 64.
// 256 threads; each thread computes 8 rows x (M/32) cols.
template <int K, int M, bool BIAS, bool RELU>
__global__ void gemm_kernel(const float* __restrict__ Xp, const float* __restrict__ W,
                            const float* __restrict__ bias, float* __restrict__ outp,
                            int n, int xsel, int osel) {
    __shared__ float Ws[64 * M];
    __shared__ float Xs[64 * 64];
    const float* X = (xsel == 2) ? g_H : Xp;
    float* out;
    switch (osel) {
        case 0: out = g_XL1; break;
        case 1: out = g_XR1; break;
        case 3: out = g_XL2; break;
        case 4: out = g_XR2; break;
        case 5: out = g_T;   break;
        default: out = outp; break;
    }
    constexpr int TN = M / 32;
    int tid  = threadIdx.x;
    int lane = tid & 31;
    int rg   = tid >> 5;
    int row0 = blockIdx.x * 64;

    float acc[8][TN];
#pragma unroll
    for (int i = 0; i < 8; i++)
#pragma unroll
        for (int j = 0; j < TN; j++) acc[i][j] = 0.f;

    for (int k0 = 0; k0 < K; k0 += 64) {
        if (k0) __syncthreads();
        for (int i = tid; i < 64 * M; i += 256) {
            int kk = i / M, mm = i - kk * M;
            Ws[i] = W[(size_t)(k0 + kk) * M + mm];
        }
        for (int i = tid; i < 64 * 64; i += 256) {
            int r = i >> 6, k = i & 63;
            int row = row0 + r;
            Xs[i] = (row < n) ? X[(size_t)row * K + k0 + k] : 0.f;
        }
        __syncthreads();

#pragma unroll 4
        for (int k = 0; k < 64; k++) {
            float wv[TN];
            if constexpr (TN == 4) {
                float4 w4 = *(const float4*)&Ws[k * M + lane * 4];
                wv[0] = w4.x; wv[1] = w4.y; wv[2] = w4.z; wv[3] = w4.w;
            } else {
                float2 w2 = *(const float2*)&Ws[k * M + lane * 2];
                wv[0] = w2.x; wv[1] = w2.y;
            }
#pragma unroll
            for (int i = 0; i < 8; i++) {
                float xv = Xs[(rg * 8 + i) * 64 + k];
#pragma unroll
                for (int j = 0; j < TN; j++) acc[i][j] += xv * wv[j];
            }
        }
    }

    float bv[TN];
#pragma unroll
    for (int j = 0; j < TN; j++) bv[j] = BIAS ? bias[lane * TN + j] : 0.f;

#pragma unroll
    for (int i = 0; i < 8; i++) {
        int row = row0 + rg * 8 + i;
        if (row < n) {
#pragma unroll
            for (int j = 0; j < TN; j++) {
                float v = acc[i][j] + bv[j];
                if constexpr (RELU) v = fmaxf(v, 0.f);
                out[(size_t)row * M + lane * TN + j] = v;
            }
        }
    }
}

// ---------------- GATv2 aggregation: warp-per-node, fixed-reference softmax ----
// Same loop structure / register profile as the R4 online-softmax version, but
// with a fixed exp reference (self-loop logit): per edge this drops one
// __expf, the fmaxf chain, and V rescale FMAs. No unrolling (keeps occupancy).
template <int V>
__device__ __forceinline__ void ldv(float* d, const float* p) {
    if constexpr (V == 4) {
        float4 a = *(const float4*)p;
        d[0] = a.x; d[1] = a.y; d[2] = a.z; d[3] = a.w;
    } else {
        float2 a = *(const float2*)p;
        d[0] = a.x; d[1] = a.y;
    }
}

// LAYER 1: XL=g_XL1, XR=g_XR1, out=g_H; LAYER 2: XL=g_XL2, XR=g_XR2, out=param
template <int H, int C, bool RELU, int LAYER>
__global__ void gat_agg_kernel(const float* __restrict__ att, const float* __restrict__ bias,
                               float* __restrict__ outp, int n) {
    constexpr int D   = H * C;
    constexpr int V   = D / 32;
    constexpr int LPH = C / V;
    const float* XL = (LAYER == 1) ? g_XL1 : g_XL2;
    const float* XR = (LAYER == 1) ? g_XR1 : g_XR2;
    float* out      = (LAYER == 1) ? g_H   : outp;

    int w    = (blockIdx.x * blockDim.x + threadIdx.x) >> 5;
    int lane = threadIdx.x & 31;
    if (w >= n) return;

    float vr[V], vi[V], av[V], acc[V];
    ldv<V>(vr, XR + (size_t)w * D + lane * V);
    ldv<V>(vi, XL + (size_t)w * D + lane * V);
    ldv<V>(av, att + lane * V);

    // self-loop logit as fixed exp reference (softmax shift-invariant; logits
    // are O(10) so exp(pl - pself) cannot overflow fp32)
    float pself = 0.f;
#pragma unroll
    for (int v = 0; v < V; v++) {
        float e = vi[v] + vr[v];
        e = e > 0.f ? e : 0.2f * e;
        pself += e * av[v];
    }
#pragma unroll
    for (int off = 1; off < LPH; off <<= 1)
        pself += __shfl_xor_sync(0xffffffffu, pself, off);

    float s = 1.f;
#pragma unroll
    for (int v = 0; v < V; v++) acc[v] = vi[v];

    int beg = g_rowptr[w], end = g_rowptr[w + 1];
    for (int base = beg; base < end; base += 32) {
        int myidx = 0;
        if (base + lane < end) myidx = g_csr[base + lane];
        int cnt = min(32, end - base);
        for (int j = 0; j < cnt; j++) {
            int sidx = __shfl_sync(0xffffffffu, myidx, j);
            float xv[V];
            ldv<V>(xv, XL + (size_t)sidx * D + lane * V);
            float pl = 0.f;
#pragma unroll
            for (int v = 0; v < V; v++) {
                float e = xv[v] + vr[v];
                e = e > 0.f ? e : 0.2f * e;
                pl += e * av[v];
            }
#pragma unroll
            for (int off = 1; off < LPH; off <<= 1)
                pl += __shfl_xor_sync(0xffffffffu, pl, off);
            float ep = __expf(pl - pself);
            s += ep;
#pragma unroll
            for (int v = 0; v < V; v++) acc[v] += ep * xv[v];
        }
    }

    float inv = 1.f / s;
#pragma unroll
    for (int v = 0; v < V; v++) {
        float o = acc[v] * inv + bias[lane * V + v];
        if constexpr (RELU) o = fmaxf(o, 0.f);
        acc[v] = o;
    }
    float* op = out + (size_t)w * D + lane * V;
    if constexpr (V == 4) *(float4*)op = make_float4(acc[0], acc[1], acc[2], acc[3]);
    else                  *(float2*)op = make_float2(acc[0], acc[1]);
}

// ---------------- final tiny classifier layer: logits = g_T @ Wc2 + bc2 --------
__global__ void logits_kernel(const float* __restrict__ Wc2, const float* __restrict__ bc2,
                              float* __restrict__ lg, int n) {
    int w    = (blockIdx.x * blockDim.x + threadIdx.x) >> 5;
    int lane = threadIdx.x & 31;
    if (w >= n) return;
    float4 t = *(const float4*)&g_T[(size_t)w * 128 + lane * 4];
    int c = lane * 4;
    float l0 = t.x * Wc2[c * 2]           + t.y * Wc2[(c + 1) * 2]
             + t.z * Wc2[(c + 2) * 2]     + t.w * Wc2[(c + 3) * 2];
    float l1 = t.x * Wc2[c * 2 + 1]       + t.y * Wc2[(c + 1) * 2 + 1]
             + t.z * Wc2[(c + 2) * 2 + 1] + t.w * Wc2[(c + 3) * 2 + 1];
#pragma unroll
    for (int off = 16; off >= 1; off >>= 1) {
        l0 += __shfl_xor_sync(0xffffffffu, l0, off);
        l1 += __shfl_xor_sync(0xffffffffu, l1, off);
    }
    if (lane == 0) {
        lg[(size_t)w * 2 + 0] = l0 + bc2[0];
        lg[(size_t)w * 2 + 1] = l1 + bc2[1];
    }
}

// ---------------- launch --------------------------------------------------------
extern "C" void kernel_launch(void* const* d_in, const int* in_sizes, int n_in,
                              void* d_out, int out_size) {
    const float* x    = (const float*)d_in[0];
    const void*  ei   = d_in[1];
    const float* Wl1  = (const float*)d_in[3];
    const float* Wr1  = (const float*)d_in[4];
    const float* att1 = (const float*)d_in[5];
    const float* b1   = (const float*)d_in[6];
    const float* Wl2  = (const float*)d_in[7];
    const float* Wr2  = (const float*)d_in[8];
    const float* att2 = (const float*)d_in[9];
    const float* b2   = (const float*)d_in[10];
    const float* Wc1  = (const float*)d_in[15];
    const float* bc1  = (const float*)d_in[16];
    const float* Wc2  = (const float*)d_in[17];
    const float* bc2  = (const float*)d_in[18];

    int N = in_sizes[0] / 128;
    int E = in_sizes[1] / 2;
    float* out = (float*)d_out;
    float* emb = out;                       // [N, 64]
    float* lg  = out + (size_t)N * 64;      // [N, 2]

    // ---- CSR build (shared by both GAT layers) ----
    zero_detect_kernel<<<(N + 255) / 256, 256>>>((const long long*)ei, E, N);
    hist_kernel<<<(E + 255) / 256, 256>>>(ei, E, N);
    int nblk = (N + 1023) / 1024;
    scan1_kernel<<<nblk, 1024>>>(N, 0);
    scan1_kernel<<<1, 1024>>>(nblk, 1);
    scan3_kernel<<<(N + 255) / 256, 256>>>(N);
    scatter_kernel<<<(E + 255) / 256, 256>>>(E);

    int gblk = (N + 63) / 64;
    int ablk = ((N * 32) + 255) / 256;

    // ---- layer 1 ----
    gemm_kernel<128, 128, false, false><<<gblk, 256>>>(x, Wl1, nullptr, nullptr, N, -1, 0);
    gemm_kernel<128, 128, false, false><<<gblk, 256>>>(x, Wr1, nullptr, nullptr, N, -1, 1);
    gat_agg_kernel<8, 16, true, 1><<<ablk, 256>>>(att1, b1, nullptr, N);

    // ---- layer 2 ----
    gemm_kernel<128, 64, false, false><<<gblk, 256>>>(nullptr, Wl2, nullptr, nullptr, N, 2, 3);
    gemm_kernel<128, 64, false, false><<<gblk, 256>>>(nullptr, Wr2, nullptr, nullptr, N, 2, 4);
    gat_agg_kernel<1, 64, false, 2><<<ablk, 256>>>(att2, b2, emb, N);

    // ---- classifier ----
    if (out_size >= N * 66) {
        gemm_kernel<64, 128, true, true><<<gblk, 256>>>(emb, Wc1, bc1, nullptr, N, -1, 5);
        logits_kernel<<<ablk, 256>>>(Wc2, bc2, lg, N);
    }
}

// round 8
// speedup vs baseline: 2.0640x; 2.0640x over previous
#include <cuda_runtime.h>
#include <math.h>

#define NMAX 50000
#define EMAX 800000

// ---------------- scratch (static device globals; no allocations) -------------
__device__ float g_XL1[NMAX * 128];
__device__ float g_XR1[NMAX * 128];
__device__ float g_H  [NMAX * 128];
__device__ float g_XL2[NMAX * 64];
__device__ float g_XR2[NMAX * 64];
__device__ float g_T  [NMAX * 128];
__device__ int   g_src[EMAX];
__device__ int   g_dst[EMAX];
__device__ int   g_csr[EMAX];
__device__ int   g_cnt[NMAX];
__device__ int   g_incl[NMAX];
__device__ int   g_rowptr[NMAX + 1];
__device__ int   g_cursor[NMAX + 2];
__device__ int   g_bsum[1024];
__device__ int   g_dummy[4];
__device__ int   g_is64;

// ---------------- zero + edge_index dtype detection ----------------------------
__global__ void zero_detect_kernel(const long long* __restrict__ ei, int E, int n) {
    int g = blockIdx.x * blockDim.x + threadIdx.x;
    if (g < n) g_cnt[g] = 0;
    if (g == 0) {
        int ok = 1;
        int m = E < 64 ? E : 64;
        for (int i = 0; i < m; i++) {
            long long v = ei[i];
            if (v < 0 || v >= NMAX) { ok = 0; break; }
        }
        g_is64 = ok;
    }
}

__global__ void hist_kernel(const void* __restrict__ eiv, int E, int n) {
    int e = blockIdx.x * blockDim.x + threadIdx.x;
    if (e >= E) return;
    int s, d;
    if (g_is64) {
        const long long* ei = (const long long*)eiv;
        s = (int)ei[e];
        d = (int)ei[(size_t)E + e];
    } else {
        const int* ei = (const int*)eiv;
        s = ei[e];
        d = ei[E + e];
    }
    if ((unsigned)s >= (unsigned)n || (unsigned)d >= (unsigned)n) { s = 0; d = 0; }
    g_src[e] = s;
    g_dst[e] = d;
    atomicAdd(&g_cnt[d], 1);
}

__global__ void scan1_kernel(int n, int phase) {
    __shared__ int sh[1024];
    const int* in = (phase == 0) ? g_cnt : g_bsum;
    int* incl     = (phase == 0) ? g_incl : g_bsum;
    int* bsum     = (phase == 0) ? g_bsum : g_dummy;
    int g = blockIdx.x * 1024 + threadIdx.x;
    int v = (g < n) ? in[g] : 0;
    sh[threadIdx.x] = v;
    __syncthreads();
    for (int off = 1; off < 1024; off <<= 1) {
        int t = (threadIdx.x >= off) ? sh[threadIdx.x - off] : 0;
        __syncthreads();
        sh[threadIdx.x] += t;
        __syncthreads();
    }
    if (g < n) incl[g] = sh[threadIdx.x];
    if (threadIdx.x == 1023) bsum[blockIdx.x] = sh[1023];
}

__global__ void scan3_kernel(int n) {
    int g = blockIdx.x * blockDim.x + threadIdx.x;
    if (g == 0) { g_rowptr[0] = 0; g_cursor[0] = 0; }
    if (g < n) {
        int b = g >> 10;
        int v = g_incl[g] + (b > 0 ? g_bsum[b - 1] : 0);
        g_rowptr[g + 1] = v;
        g_cursor[g + 1] = v;
    }
}

__global__ void scatter_kernel(int E) {
    int e = blockIdx.x * blockDim.x + threadIdx.x;
    if (e >= E) return;
    int d = g_dst[e];
    int pos = atomicAdd(&g_cursor[d], 1);
    g_csr[pos] = g_src[e];
}

// ---------------- tf32 tensor-core GEMM ----------------------------------------
__device__ __forceinline__ unsigned f2tf32(float f) {
    unsigned u;
    asm("cvt.rna.tf32.f32 %0, %1;" : "=r"(u) : "f"(f));
    return u;
}

__device__ __forceinline__ void mma_tf32(float* c, unsigned a0, unsigned a1,
                                         unsigned a2, unsigned a3,
                                         unsigned b0, unsigned b1) {
    asm volatile(
        "mma.sync.aligned.m16n8k8.row.col.f32.tf32.tf32.f32 "
        "{%0,%1,%2,%3}, {%4,%5,%6,%7}, {%8,%9}, {%0,%1,%2,%3};\n"
        : "+f"(c[0]), "+f"(c[1]), "+f"(c[2]), "+f"(c[3])
        : "r"(a0), "r"(a1), "r"(a2), "r"(a3), "r"(b0), "r"(b1));
}

// out[N x M] = X[N x K] @ W[K x M] (+bias,relu), tf32 mma.
// 256 threads = 8 warps; warp tile 16 rows x 64 cols; KC=32 K-chunks.
// Conflict-free smem: Xs stride 36 (==4 mod 32), Ws stride M+8 (==8 mod 32).
// xsel: 2 -> X = g_H, else Xp.
// osel: 0 g_XL1, 1 g_XR1, 3 g_XL2, 4 g_XR2, 5 g_T, else emb param unused here.
template <int K, int M, bool BIAS, bool RELU>
__global__ void mma_gemm_kernel(const float* __restrict__ Xp, const float* __restrict__ W,
                                const float* __restrict__ bias, int n, int xsel, int osel) {
    constexpr int KC  = 32;
    constexpr int KCp = 36;           // 36 % 32 == 4 -> A frag conflict-free
    constexpr int Mp  = M + 8;        // (M+8) % 32 == 8 -> B frag conflict-free
    constexpr int WC  = M / 64;       // warps per col group (128->2, 64->1)
    constexpr int RB  = (8 / WC) * 16;// rows per block (64 / 128)
    constexpr int NC  = K / KC;

    __shared__ unsigned Ws[KC * Mp];
    __shared__ unsigned Xs[RB * KCp];

    const float* X = (xsel == 2) ? g_H : Xp;
    float* out;
    switch (osel) {
        case 0: out = g_XL1; break;
        case 1: out = g_XR1; break;
        case 3: out = g_XL2; break;
        case 4: out = g_XR2; break;
        default: out = g_T;  break;
    }

    int tid  = threadIdx.x;
    int lane = tid & 31;
    int wid  = tid >> 5;
    int g    = lane >> 2;          // groupID 0..7
    int t    = lane & 3;           // thread-in-group 0..3
    int wr   = wid / WC;           // warp row group
    int n0w  = (wid % WC) * 64;    // warp col base
    int row0 = blockIdx.x * RB;

    float acc[8][4];
#pragma unroll
    for (int i = 0; i < 8; i++)
#pragma unroll
        for (int j = 0; j < 4; j++) acc[i][j] = 0.f;

    for (int c0 = 0; c0 < NC; c0++) {
        int k0 = c0 * KC;
        if (c0) __syncthreads();
        // stage W chunk [KC x M] (no transpose; coalesced; conflict-free stores)
        for (int i = tid; i < KC * M; i += 256) {
            int k = i / M, m = i - k * M;
            Ws[k * Mp + m] = f2tf32(W[(size_t)(k0 + k) * M + m]);
        }
        // stage X tile [RB x KC]
        for (int i = tid; i < RB * KC; i += 256) {
            int r = i >> 5, k = i & 31;
            int row = row0 + r;
            float v = (row < n) ? X[(size_t)row * K + k0 + k] : 0.f;
            Xs[r * KCp + k] = f2tf32(v);
        }
        __syncthreads();

#pragma unroll
        for (int ks = 0; ks < KC / 8; ks++) {
            int kk = ks * 8;
            int ar = wr * 16 + g;
            unsigned a0 = Xs[ar * KCp + kk + t];
            unsigned a1 = Xs[(ar + 8) * KCp + kk + t];
            unsigned a2 = Xs[ar * KCp + kk + t + 4];
            unsigned a3 = Xs[(ar + 8) * KCp + kk + t + 4];
#pragma unroll
            for (int nt = 0; nt < 8; nt++) {
                unsigned b0 = Ws[(kk + t) * Mp + n0w + nt * 8 + g];
                unsigned b1 = Ws[(kk + t + 4) * Mp + n0w + nt * 8 + g];
                mma_tf32(acc[nt], a0, a1, a2, a3, b0, b1);
            }
        }
    }

    // epilogue: c0/c1 -> (row, 2t / 2t+1), c2/c3 -> (row+8, same cols)
    int r0 = row0 + wr * 16 + g;
    int r1 = r0 + 8;
#pragma unroll
    for (int nt = 0; nt < 8; nt++) {
        int c = n0w + nt * 8 + 2 * t;
        float bv0 = BIAS ? bias[c]     : 0.f;
        float bv1 = BIAS ? bias[c + 1] : 0.f;
        float v0 = acc[nt][0] + bv0, v1 = acc[nt][1] + bv1;
        float v2 = acc[nt][2] + bv0, v3 = acc[nt][3] + bv1;
        if constexpr (RELU) {
            v0 = fmaxf(v0, 0.f); v1 = fmaxf(v1, 0.f);
            v2 = fmaxf(v2, 0.f); v3 = fmaxf(v3, 0.f);
        }
        if (r0 < n) *(float2*)&out[(size_t)r0 * M + c] = make_float2(v0, v1);
        if (r1 < n) *(float2*)&out[(size_t)r1 * M + c] = make_float2(v2, v3);
    }
}

// ---------------- GATv2 aggregation: warp-per-node, fixed-reference softmax ----
template <int V>
__device__ __forceinline__ void ldv(float* d, const float* p) {
    if constexpr (V == 4) {
        float4 a = *(const float4*)p;
        d[0] = a.x; d[1] = a.y; d[2] = a.z; d[3] = a.w;
    } else {
        float2 a = *(const float2*)p;
        d[0] = a.x; d[1] = a.y;
    }
}

// LAYER 1: XL=g_XL1, XR=g_XR1, out=g_H; LAYER 2: XL=g_XL2, XR=g_XR2, out=param
template <int H, int C, bool RELU, int LAYER>
__global__ void gat_agg_kernel(const float* __restrict__ att, const float* __restrict__ bias,
                               float* __restrict__ outp, int n) {
    constexpr int D   = H * C;
    constexpr int V   = D / 32;
    constexpr int LPH = C / V;
    const float* XL = (LAYER == 1) ? g_XL1 : g_XL2;
    const float* XR = (LAYER == 1) ? g_XR1 : g_XR2;
    float* out      = (LAYER == 1) ? g_H   : outp;

    int w    = (blockIdx.x * blockDim.x + threadIdx.x) >> 5;
    int lane = threadIdx.x & 31;
    if (w >= n) return;

    float vr[V], vi[V], av[V], acc[V];
    ldv<V>(vr, XR + (size_t)w * D + lane * V);
    ldv<V>(vi, XL + (size_t)w * D + lane * V);
    ldv<V>(av, att + lane * V);

    float pself = 0.f;
#pragma unroll
    for (int v = 0; v < V; v++) {
        float e = vi[v] + vr[v];
        e = e > 0.f ? e : 0.2f * e;
        pself += e * av[v];
    }
#pragma unroll
    for (int off = 1; off < LPH; off <<= 1)
        pself += __shfl_xor_sync(0xffffffffu, pself, off);

    float s = 1.f;
#pragma unroll
    for (int v = 0; v < V; v++) acc[v] = vi[v];

    int beg = g_rowptr[w], end = g_rowptr[w + 1];
    for (int base = beg; base < end; base += 32) {
        int myidx = 0;
        if (base + lane < end) myidx = g_csr[base + lane];
        int cnt = min(32, end - base);
        for (int j = 0; j < cnt; j++) {
            int sidx = __shfl_sync(0xffffffffu, myidx, j);
            float xv[V];
            ldv<V>(xv, XL + (size_t)sidx * D + lane * V);
            float pl = 0.f;
#pragma unroll
            for (int v = 0; v < V; v++) {
                float e = xv[v] + vr[v];
                e = e > 0.f ? e : 0.2f * e;
                pl += e * av[v];
            }
#pragma unroll
            for (int off = 1; off < LPH; off <<= 1)
                pl += __shfl_xor_sync(0xffffffffu, pl, off);
            float ep = __expf(pl - pself);
            s += ep;
#pragma unroll
            for (int v = 0; v < V; v++) acc[v] += ep * xv[v];
        }
    }

    float inv = 1.f / s;
#pragma unroll
    for (int v = 0; v < V; v++) {
        float o = acc[v] * inv + bias[lane * V + v];
        if constexpr (RELU) o = fmaxf(o, 0.f);
        acc[v] = o;
    }
    float* op = out + (size_t)w * D + lane * V;
    if constexpr (V == 4) *(float4*)op = make_float4(acc[0], acc[1], acc[2], acc[3]);
    else                  *(float2*)op = make_float2(acc[0], acc[1]);
}

// ---------------- final tiny classifier layer: logits = g_T @ Wc2 + bc2 --------
__global__ void logits_kernel(const float* __restrict__ Wc2, const float* __restrict__ bc2,
                              float* __restrict__ lg, int n) {
    int w    = (blockIdx.x * blockDim.x + threadIdx.x) >> 5;
    int lane = threadIdx.x & 31;
    if (w >= n) return;
    float4 t = *(const float4*)&g_T[(size_t)w * 128 + lane * 4];
    int c = lane * 4;
    float l0 = t.x * Wc2[c * 2]           + t.y * Wc2[(c + 1) * 2]
             + t.z * Wc2[(c + 2) * 2]     + t.w * Wc2[(c + 3) * 2];
    float l1 = t.x * Wc2[c * 2 + 1]       + t.y * Wc2[(c + 1) * 2 + 1]
             + t.z * Wc2[(c + 2) * 2 + 1] + t.w * Wc2[(c + 3) * 2 + 1];
#pragma unroll
    for (int off = 16; off >= 1; off >>= 1) {
        l0 += __shfl_xor_sync(0xffffffffu, l0, off);
        l1 += __shfl_xor_sync(0xffffffffu, l1, off);
    }
    if (lane == 0) {
        lg[(size_t)w * 2 + 0] = l0 + bc2[0];
        lg[(size_t)w * 2 + 1] = l1 + bc2[1];
    }
}

// ---------------- launch --------------------------------------------------------
extern "C" void kernel_launch(void* const* d_in, const int* in_sizes, int n_in,
                              void* d_out, int out_size) {
    const float* x    = (const float*)d_in[0];
    const void*  ei   = d_in[1];
    const float* Wl1  = (const float*)d_in[3];
    const float* Wr1  = (const float*)d_in[4];
    const float* att1 = (const float*)d_in[5];
    const float* b1   = (const float*)d_in[6];
    const float* Wl2  = (const float*)d_in[7];
    const float* Wr2  = (const float*)d_in[8];
    const float* att2 = (const float*)d_in[9];
    const float* b2   = (const float*)d_in[10];
    const float* Wc1  = (const float*)d_in[15];
    const float* bc1  = (const float*)d_in[16];
    const float* Wc2  = (const float*)d_in[17];
    const float* bc2  = (const float*)d_in[18];

    int N = in_sizes[0] / 128;
    int E = in_sizes[1] / 2;
    float* out = (float*)d_out;
    float* emb = out;                       // [N, 64]
    float* lg  = out + (size_t)N * 64;      // [N, 2]

    int ablk = ((N * 32) + 255) / 256;
    int g64  = (N + 63) / 64;
    int g128 = (N + 127) / 128;
    int nblk = (N + 1023) / 1024;

    // CSR build interleaved with layer-1 GEMMs (GEMMs don't need the CSR; this
    // also puts a GEMM in the ncu capture window)
    zero_detect_kernel<<<(N + 255) / 256, 256>>>((const long long*)ei, E, N);      // 0
    hist_kernel<<<(E + 255) / 256, 256>>>(ei, E, N);                               // 1
    mma_gemm_kernel<128, 128, false, false><<<g64, 256>>>(x, Wl1, nullptr, N, -1, 0); // 2
    mma_gemm_kernel<128, 128, false, false><<<g64, 256>>>(x, Wr1, nullptr, N, -1, 1); // 3
    scan1_kernel<<<nblk, 1024>>>(N, 0);                                            // 4
    scan1_kernel<<<1, 1024>>>(nblk, 1);                                            // 5
    scan3_kernel<<<(N + 255) / 256, 256>>>(N);                                     // 6
    scatter_kernel<<<(E + 255) / 256, 256>>>(E);                                   // 7

    // layer 1 aggregation
    gat_agg_kernel<8, 16, true, 1><<<ablk, 256>>>(att1, b1, nullptr, N);           // 8

    // layer 2
    mma_gemm_kernel<128, 64, false, false><<<g128, 256>>>(nullptr, Wl2, nullptr, N, 2, 3);
    mma_gemm_kernel<128, 64, false, false><<<g128, 256>>>(nullptr, Wr2, nullptr, N, 2, 4);
    gat_agg_kernel<1, 64, false, 2><<<ablk, 256>>>(att2, b2, emb, N);

    // classifier
    if (out_size >= N * 66) {
        mma_gemm_kernel<64, 128, true, true><<<g64, 256>>>(emb, Wc1, bc1, N, -1, 5);
        logits_kernel<<<ablk, 256>>>(Wc2, bc2, lg, N);
    }
}

// round 10
// speedup vs baseline: 2.2297x; 1.0803x over previous
#include <cuda_runtime.h>
#include <math.h>

#define NMAX 50000
#define EMAX 800000

// ---------------- scratch (static device globals; no allocations) -------------
__device__ float g_XL1[NMAX * 128];
__device__ float g_XR1[NMAX * 128];
__device__ float g_H  [NMAX * 128];
__device__ float g_XL2[NMAX * 64];
__device__ float g_XR2[NMAX * 64];
__device__ float g_T  [NMAX * 128];
__device__ int   g_src[EMAX];
__device__ int   g_dst[EMAX];
__device__ int   g_csr[EMAX];
__device__ int   g_cnt[NMAX];
__device__ int   g_incl[NMAX];
__device__ int   g_rowptr[NMAX + 1];
__device__ int   g_cursor[NMAX + 2];
__device__ int   g_bsum[1024];
__device__ int   g_dummy[4];
__device__ int   g_is64;

// ---------------- zero + edge_index dtype detection ----------------------------
__global__ void zero_detect_kernel(const long long* __restrict__ ei, int E, int n) {
    int g = blockIdx.x * blockDim.x + threadIdx.x;
    if (g < n) g_cnt[g] = 0;
    if (g == 0) {
        int ok = 1;
        int m = E < 64 ? E : 64;
        for (int i = 0; i < m; i++) {
            long long v = ei[i];
            if (v < 0 || v >= NMAX) { ok = 0; break; }
        }
        g_is64 = ok;
    }
}

__global__ void hist_kernel(const void* __restrict__ eiv, int E, int n) {
    int e = blockIdx.x * blockDim.x + threadIdx.x;
    if (e >= E) return;
    int s, d;
    if (g_is64) {
        const long long* ei = (const long long*)eiv;
        s = (int)ei[e];
        d = (int)ei[(size_t)E + e];
    } else {
        const int* ei = (const int*)eiv;
        s = ei[e];
        d = ei[E + e];
    }
    if ((unsigned)s >= (unsigned)n || (unsigned)d >= (unsigned)n) { s = 0; d = 0; }
    g_src[e] = s;
    g_dst[e] = d;
    atomicAdd(&g_cnt[d], 1);
}

__global__ void scan1_kernel(int n, int phase) {
    __shared__ int sh[1024];
    const int* in = (phase == 0) ? g_cnt : g_bsum;
    int* incl     = (phase == 0) ? g_incl : g_bsum;
    int* bsum     = (phase == 0) ? g_bsum : g_dummy;
    int g = blockIdx.x * 1024 + threadIdx.x;
    int v = (g < n) ? in[g] : 0;
    sh[threadIdx.x] = v;
    __syncthreads();
    for (int off = 1; off < 1024; off <<= 1) {
        int t = (threadIdx.x >= off) ? sh[threadIdx.x - off] : 0;
        __syncthreads();
        sh[threadIdx.x] += t;
        __syncthreads();
    }
    if (g < n) incl[g] = sh[threadIdx.x];
    if (threadIdx.x == 1023) bsum[blockIdx.x] = sh[1023];
}

__global__ void scan3_kernel(int n) {
    int g = blockIdx.x * blockDim.x + threadIdx.x;
    if (g == 0) { g_rowptr[0] = 0; g_cursor[0] = 0; }
    if (g < n) {
        int b = g >> 10;
        int v = g_incl[g] + (b > 0 ? g_bsum[b - 1] : 0);
        g_rowptr[g + 1] = v;
        g_cursor[g + 1] = v;
    }
}

__global__ void scatter_kernel(int E) {
    int e = blockIdx.x * blockDim.x + threadIdx.x;
    if (e >= E) return;
    int d = g_dst[e];
    int pos = atomicAdd(&g_cursor[d], 1);
    g_csr[pos] = g_src[e];
}

// ---------------- tf32 tensor-core GEMM (double-buffered, pipelined) -----------
__device__ __forceinline__ unsigned f2tf32(float f) {
    unsigned u;
    asm("cvt.rna.tf32.f32 %0, %1;" : "=r"(u) : "f"(f));
    return u;
}

__device__ __forceinline__ void mma_tf32(float* c, unsigned a0, unsigned a1,
                                         unsigned a2, unsigned a3,
                                         unsigned b0, unsigned b1) {
    asm volatile(
        "mma.sync.aligned.m16n8k8.row.col.f32.tf32.tf32.f32 "
        "{%0,%1,%2,%3}, {%4,%5,%6,%7}, {%8,%9}, {%0,%1,%2,%3};\n"
        : "+f"(c[0]), "+f"(c[1]), "+f"(c[2]), "+f"(c[3])
        : "r"(a0), "r"(a1), "r"(a2), "r"(a3), "r"(b0), "r"(b1));
}

// out[N x M] = X[N x K] @ W[K x M] (+bias,relu), tf32 mma.
// 256 threads = 8 warps; warp tile 16 x 64; KC=16 chunks, double-buffered smem,
// next chunk's LDGs prefetched into registers during the current chunk's mmas.
// Conflict-free smem: Xs stride 20 (g*20+t distinct mod 32), Ws stride M+8
// (8t+g distinct mod 32).
// xsel: 2 -> X = g_H, else Xp. osel: 0 g_XL1, 1 g_XR1, 3 g_XL2, 4 g_XR2, 5 g_T.
template <int K, int M, bool BIAS, bool RELU>
__global__ void mma_gemm_kernel(const float* __restrict__ Xp, const float* __restrict__ W,
                                const float* __restrict__ bias, int n, int xsel, int osel) {
    constexpr int KC  = 16;
    constexpr int KCp = 20;
    constexpr int Mp  = M + 8;
    constexpr int WC  = M / 64;         // warps per col group (128->2, 64->1)
    constexpr int RB  = (8 / WC) * 16;  // rows per block (64 / 128)
    constexpr int NC  = K / KC;
    constexpr int WI  = KC * M / 256;   // W elems per thread per chunk
    constexpr int XI  = RB * KC / 256;  // X elems per thread per chunk

    __shared__ unsigned Ws[2][KC * Mp];
    __shared__ unsigned Xs[2][RB * KCp];

    const float* X = (xsel == 2) ? g_H : Xp;
    float* out;
    switch (osel) {
        case 0: out = g_XL1; break;
        case 1: out = g_XR1; break;
        case 3: out = g_XL2; break;
        case 4: out = g_XR2; break;
        default: out = g_T;  break;
    }

    int tid  = threadIdx.x;
    int lane = tid & 31;
    int wid  = tid >> 5;
    int g    = lane >> 2;
    int t    = lane & 3;
    int wr   = wid / WC;
    int n0w  = (wid % WC) * 64;
    int row0 = blockIdx.x * RB;

    float wreg[WI], xreg[XI];

#define LDG_CHUNK(k0)                                                          \
    {                                                                          \
        _Pragma("unroll")                                                      \
        for (int u = 0; u < WI; u++) {                                         \
            int i = tid + u * 256;                                             \
            int k = i / M, m = i - k * M;                                      \
            wreg[u] = W[(size_t)((k0) + k) * M + m];                           \
        }                                                                      \
        _Pragma("unroll")                                                      \
        for (int u = 0; u < XI; u++) {                                         \
            int i = tid + u * 256;                                             \
            int r = i >> 4, k = i & 15;                                        \
            int row = row0 + r;                                                \
            xreg[u] = (row < n) ? X[(size_t)row * K + (k0) + k] : 0.f;         \
        }                                                                      \
    }

#define STS_CHUNK(b)                                                           \
    {                                                                          \
        _Pragma("unroll")                                                      \
        for (int u = 0; u < WI; u++) {                                         \
            int i = tid + u * 256;                                             \
            int k = i / M, m = i - k * M;                                      \
            Ws[b][k * Mp + m] = f2tf32(wreg[u]);                               \
        }                                                                      \
        _Pragma("unroll")                                                      \
        for (int u = 0; u < XI; u++) {                                         \
            int i = tid + u * 256;                                             \
            int r = i >> 4, k = i & 15;                                        \
            Xs[b][r * KCp + k] = f2tf32(xreg[u]);                              \
        }                                                                      \
    }

    float acc[8][4];
#pragma unroll
    for (int i = 0; i < 8; i++)
#pragma unroll
        for (int j = 0; j < 4; j++) acc[i][j] = 0.f;

    LDG_CHUNK(0);
    STS_CHUNK(0);
    __syncthreads();

    for (int c = 0; c < NC; c++) {
        if (c + 1 < NC) LDG_CHUNK((c + 1) * KC);
        int b = c & 1;
        int ar = wr * 16 + g;
#pragma unroll
        for (int ks = 0; ks < KC / 8; ks++) {
            int kk = ks * 8;
            unsigned a0 = Xs[b][ar * KCp + kk + t];
            unsigned a1 = Xs[b][(ar + 8) * KCp + kk + t];
            unsigned a2 = Xs[b][ar * KCp + kk + t + 4];
            unsigned a3 = Xs[b][(ar + 8) * KCp + kk + t + 4];
#pragma unroll
            for (int nt = 0; nt < 8; nt++) {
                unsigned b0 = Ws[b][(kk + t) * Mp + n0w + nt * 8 + g];
                unsigned b1 = Ws[b][(kk + t + 4) * Mp + n0w + nt * 8 + g];
                mma_tf32(acc[nt], a0, a1, a2, a3, b0, b1);
            }
        }
        if (c + 1 < NC) STS_CHUNK((c + 1) & 1);
        __syncthreads();
    }

#undef LDG_CHUNK
#undef STS_CHUNK

    int r0 = row0 + wr * 16 + g;
    int r1 = r0 + 8;
#pragma unroll
    for (int nt = 0; nt < 8; nt++) {
        int c = n0w + nt * 8 + 2 * t;
        float bv0 = BIAS ? bias[c]     : 0.f;
        float bv1 = BIAS ? bias[c + 1] : 0.f;
        float v0 = acc[nt][0] + bv0, v1 = acc[nt][1] + bv1;
        float v2 = acc[nt][2] + bv0, v3 = acc[nt][3] + bv1;
        if constexpr (RELU) {
            v0 = fmaxf(v0, 0.f); v1 = fmaxf(v1, 0.f);
            v2 = fmaxf(v2, 0.f); v3 = fmaxf(v3, 0.f);
        }
        if (r0 < n) *(float2*)&out[(size_t)r0 * M + c] = make_float2(v0, v1);
        if (r1 < n) *(float2*)&out[(size_t)r1 * M + c] = make_float2(v2, v3);
    }
}

// ---------------- GATv2 aggregation: warp-per-node, fixed-reference softmax ----
template <int V>
__device__ __forceinline__ void ldv(float* d, const float* p) {
    if constexpr (V == 4) {
        float4 a = *(const float4*)p;
        d[0] = a.x; d[1] = a.y; d[2] = a.z; d[3] = a.w;
    } else {
        float2 a = *(const float2*)p;
        d[0] = a.x; d[1] = a.y;
    }
}

// LAYER 1: XL=g_XL1, XR=g_XR1, out=g_H; LAYER 2: XL=g_XL2, XR=g_XR2, out=param
template <int H, int C, bool RELU, int LAYER>
__global__ void gat_agg_kernel(const float* __restrict__ att, const float* __restrict__ bias,
                               float* __restrict__ outp, int n) {
    constexpr int D   = H * C;
    constexpr int V   = D / 32;
    constexpr int LPH = C / V;
    const float* XL = (LAYER == 1) ? g_XL1 : g_XL2;
    const float* XR = (LAYER == 1) ? g_XR1 : g_XR2;
    float* out      = (LAYER == 1) ? g_H   : outp;

    int w    = (blockIdx.x * blockDim.x + threadIdx.x) >> 5;
    int lane = threadIdx.x & 31;
    if (w >= n) return;

    float vr[V], vi[V], av[V], acc[V];
    ldv<V>(vr, XR + (size_t)w * D + lane * V);
    ldv<V>(vi, XL + (size_t)w * D + lane * V);
    ldv<V>(av, att + lane * V);

    float pself = 0.f;
#pragma unroll
    for (int v = 0; v < V; v++) {
        float e = vi[v] + vr[v];
        e = e > 0.f ? e : 0.2f * e;
        pself += e * av[v];
    }
#pragma unroll
    for (int off = 1; off < LPH; off <<= 1)
        pself += __shfl_xor_sync(0xffffffffu, pself, off);

    float s = 1.f;
#pragma unroll
    for (int v = 0; v < V; v++) acc[v] = vi[v];

    int beg = g_rowptr[w], end = g_rowptr[w + 1];
    for (int base = beg; base < end; base += 32) {
        int myidx = 0;
        if (base + lane < end) myidx = g_csr[base + lane];
        int cnt = min(32, end - base);
        for (int j = 0; j < cnt; j++) {
            int sidx = __shfl_sync(0xffffffffu, myidx, j);
            float xv[V];
            ldv<V>(xv, XL + (size_t)sidx * D + lane * V);
            float pl = 0.f;
#pragma unroll
            for (int v = 0; v < V; v++) {
                float e = xv[v] + vr[v];
                e = e > 0.f ? e : 0.2f * e;
                pl += e * av[v];
            }
#pragma unroll
            for (int off = 1; off < LPH; off <<= 1)
                pl += __shfl_xor_sync(0xffffffffu, pl, off);
            float ep = __expf(pl - pself);
            s += ep;
#pragma unroll
            for (int v = 0; v < V; v++) acc[v] += ep * xv[v];
        }
    }

    float inv = 1.f / s;
#pragma unroll
    for (int v = 0; v < V; v++) {
        float o = acc[v] * inv + bias[lane * V + v];
        if constexpr (RELU) o = fmaxf(o, 0.f);
        acc[v] = o;
    }
    float* op = out + (size_t)w * D + lane * V;
    if constexpr (V == 4) *(float4*)op = make_float4(acc[0], acc[1], acc[2], acc[3]);
    else                  *(float2*)op = make_float2(acc[0], acc[1]);
}

// ---------------- final tiny classifier layer: logits = g_T @ Wc2 + bc2 --------
__global__ void logits_kernel(const float* __restrict__ Wc2, const float* __restrict__ bc2,
                              float* __restrict__ lg, int n) {
    int w    = (blockIdx.x * blockDim.x + threadIdx.x) >> 5;
    int lane = threadIdx.x & 31;
    if (w >= n) return;
    float4 t = *(const float4*)&g_T[(size_t)w * 128 + lane * 4];
    int c = lane * 4;
    float l0 = t.x * Wc2[c * 2]           + t.y * Wc2[(c + 1) * 2]
             + t.z * Wc2[(c + 2) * 2]     + t.w * Wc2[(c + 3) * 2];
    float l1 = t.x * Wc2[c * 2 + 1]       + t.y * Wc2[(c + 1) * 2 + 1]
             + t.z * Wc2[(c + 2) * 2 + 1] + t.w * Wc2[(c + 3) * 2 + 1];
#pragma unroll
    for (int off = 16; off >= 1; off >>= 1) {
        l0 += __shfl_xor_sync(0xffffffffu, l0, off);
        l1 += __shfl_xor_sync(0xffffffffu, l1, off);
    }
    if (lane == 0) {
        lg[(size_t)w * 2 + 0] = l0 + bc2[0];
        lg[(size_t)w * 2 + 1] = l1 + bc2[1];
    }
}

// ---------------- launch --------------------------------------------------------
extern "C" void kernel_launch(void* const* d_in, const int* in_sizes, int n_in,
                              void* d_out, int out_size) {
    const float* x    = (const float*)d_in[0];
    const void*  ei   = d_in[1];
    const float* Wl1  = (const float*)d_in[3];
    const float* Wr1  = (const float*)d_in[4];
    const float* att1 = (const float*)d_in[5];
    const float* b1   = (const float*)d_in[6];
    const float* Wl2  = (const float*)d_in[7];
    const float* Wr2  = (const float*)d_in[8];
    const float* att2 = (const float*)d_in[9];
    const float* b2   = (const float*)d_in[10];
    const float* Wc1  = (const float*)d_in[15];
    const float* bc1  = (const float*)d_in[16];
    const float* Wc2  = (const float*)d_in[17];
    const float* bc2  = (const float*)d_in[18];

    int N = in_sizes[0] / 128;
    int E = in_sizes[1] / 2;
    float* out = (float*)d_out;
    float* emb = out;                       // [N, 64]
    float* lg  = out + (size_t)N * 64;      // [N, 2]

    int ablk = ((N * 32) + 255) / 256;
    int g64  = (N + 63) / 64;
    int g128 = (N + 127) / 128;
    int nblk = (N + 1023) / 1024;

    // CSR build interleaved with layer-1 GEMMs (GEMMs don't need the CSR; this
    // also puts a GEMM in the ncu capture window)
    zero_detect_kernel<<<(N + 255) / 256, 256>>>((const long long*)ei, E, N);         // 0
    hist_kernel<<<(E + 255) / 256, 256>>>(ei, E, N);                                  // 1
    mma_gemm_kernel<128, 128, false, false><<<g64, 256>>>(x, Wl1, nullptr, N, -1, 0); // 2
    mma_gemm_kernel<128, 128, false, false><<<g64, 256>>>(x, Wr1, nullptr, N, -1, 1); // 3
    scan1_kernel<<<nblk, 1024>>>(N, 0);                                               // 4
    scan1_kernel<<<1, 1024>>>(nblk, 1);                                               // 5
    scan3_kernel<<<(N + 255) / 256, 256>>>(N);                                        // 6
    scatter_kernel<<<(E + 255) / 256, 256>>>(E);                                      // 7

    // layer 1 aggregation
    gat_agg_kernel<8, 16, true, 1><<<ablk, 256>>>(att1, b1, nullptr, N);              // 8

    // layer 2
    mma_gemm_kernel<128, 64, false, false><<<g128, 256>>>(nullptr, Wl2, nullptr, N, 2, 3);
    mma_gemm_kernel<128, 64, false, false><<<g128, 256>>>(nullptr, Wr2, nullptr, N, 2, 4);
    gat_agg_kernel<1, 64, false, 2><<<ablk, 256>>>(att2, b2, emb, N);

    // classifier
    if (out_size >= N * 66) {
        mma_gemm_kernel<64, 128, true, true><<<g64, 256>>>(emb, Wc1, bc1, N, -1, 5);
        logits_kernel<<<ablk, 256>>>(Wc2, bc2, lg, N);
    }
}